// round 1
// baseline (speedup 1.0000x reference)
#include <cuda_runtime.h>
#include <cstdint>

#define N_NODES 10000
#define N_EDGES 320000
#define FEAT 128
#define NCLS 64

// ---------------- scratch (no allocations allowed) ----------------
__device__ int   d_deg[N_NODES];
__device__ int   d_rowptr[N_NODES + 1];
__device__ int   d_cursor[N_NODES];
__device__ int   d_eidx[N_EDGES];   // edge ids sorted by dst (CSR)
__device__ int   d_csrc[N_EDGES];   // src[eidx[j]] pre-gathered
__device__ float d_invdeg[N_NODES];
__device__ float d_m[N_NODES * FEAT];   // node mean buffer
__device__ float d_a[N_NODES * FEAT];   // node sum buffer (GEMM input)
__device__ float d_g[N_NODES * FEAT];   // node GEMM output (a @ W^T)

__device__ __forceinline__ float4 f4add(float4 a, float4 b) {
    return make_float4(a.x + b.x, a.y + b.y, a.z + b.z, a.w + b.w);
}

// ---------------- CSR construction ----------------
__global__ void k_zero_deg() {
    int i = blockIdx.x * blockDim.x + threadIdx.x;
    if (i < N_NODES) d_deg[i] = 0;
}

__global__ void k_count(const int* __restrict__ dst) {
    int e = blockIdx.x * blockDim.x + threadIdx.x;
    if (e < N_EDGES) atomicAdd(&d_deg[dst[e]], 1);
}

// single-block scan (1024 threads x 10 items)
__global__ void k_scan() {
    __shared__ int tsum[1024];
    const int IPT = 10;
    int t = threadIdx.x;
    int base = t * IPT;
    int local[IPT];
    int s = 0;
    #pragma unroll
    for (int i = 0; i < IPT; i++) {
        int idx = base + i;
        int v = (idx < N_NODES) ? d_deg[idx] : 0;
        local[i] = s;
        s += v;
    }
    tsum[t] = s;
    __syncthreads();
    for (int d = 1; d < 1024; d <<= 1) {
        int v = (t >= d) ? tsum[t - d] : 0;
        __syncthreads();
        tsum[t] += v;
        __syncthreads();
    }
    int offset = tsum[t] - s;  // exclusive
    #pragma unroll
    for (int i = 0; i < IPT; i++) {
        int idx = base + i;
        if (idx < N_NODES) {
            int rp = offset + local[i];
            d_rowptr[idx] = rp;
            d_cursor[idx] = rp;
            d_invdeg[idx] = 1.0f / (float)d_deg[idx];
        }
    }
    if (t == 1023) d_rowptr[N_NODES] = tsum[1023];
}

__global__ void k_fill(const int* __restrict__ dst, const int* __restrict__ src) {
    int e = blockIdx.x * blockDim.x + threadIdx.x;
    if (e < N_EDGES) {
        int pos = atomicAdd(&d_cursor[dst[e]], 1);
        d_eidx[pos] = e;
        d_csrc[pos] = src[e];
    }
}

// ---------------- layer-1 step 1: m[n] = mean over in-edges of edge_feats ----------------
// warp per node, float4 per lane, unroll-4 for MLP
__global__ void k_gather_mean_edges(const float* __restrict__ ef) {
    int gw = (blockIdx.x * blockDim.x + threadIdx.x) >> 5;
    if (gw >= N_NODES) return;
    int lane = threadIdx.x & 31;
    int j = d_rowptr[gw], jend = d_rowptr[gw + 1];
    float4 a0 = {0, 0, 0, 0}, a1 = {0, 0, 0, 0}, a2 = {0, 0, 0, 0}, a3 = {0, 0, 0, 0};
    for (; j + 4 <= jend; j += 4) {
        int e0 = d_eidx[j], e1 = d_eidx[j + 1], e2 = d_eidx[j + 2], e3 = d_eidx[j + 3];
        float4 v0 = __ldg(((const float4*)(ef + (size_t)e0 * FEAT)) + lane);
        float4 v1 = __ldg(((const float4*)(ef + (size_t)e1 * FEAT)) + lane);
        float4 v2 = __ldg(((const float4*)(ef + (size_t)e2 * FEAT)) + lane);
        float4 v3 = __ldg(((const float4*)(ef + (size_t)e3 * FEAT)) + lane);
        a0 = f4add(a0, v0); a1 = f4add(a1, v1); a2 = f4add(a2, v2); a3 = f4add(a3, v3);
    }
    for (; j < jend; j++) {
        int e0 = d_eidx[j];
        a0 = f4add(a0, __ldg(((const float4*)(ef + (size_t)e0 * FEAT)) + lane));
    }
    a0 = f4add(f4add(a0, a1), f4add(a2, a3));
    float id = d_invdeg[gw];
    float4 o = make_float4(a0.x * id, a0.y * id, a0.z * id, a0.w * id);
    ((float4*)(d_m + gw * FEAT))[lane] = o;
}

// ---------------- step 2: a[n] = sum over in-edges of m[src_e] ----------------
__global__ void k_gather_sum_src() {
    int gw = (blockIdx.x * blockDim.x + threadIdx.x) >> 5;
    if (gw >= N_NODES) return;
    int lane = threadIdx.x & 31;
    int j = d_rowptr[gw], jend = d_rowptr[gw + 1];
    float4 a0 = {0, 0, 0, 0}, a1 = {0, 0, 0, 0}, a2 = {0, 0, 0, 0}, a3 = {0, 0, 0, 0};
    for (; j + 4 <= jend; j += 4) {
        int s0 = d_csrc[j], s1 = d_csrc[j + 1], s2 = d_csrc[j + 2], s3 = d_csrc[j + 3];
        float4 v0 = ((const float4*)(d_m + s0 * FEAT))[lane];
        float4 v1 = ((const float4*)(d_m + s1 * FEAT))[lane];
        float4 v2 = ((const float4*)(d_m + s2 * FEAT))[lane];
        float4 v3 = ((const float4*)(d_m + s3 * FEAT))[lane];
        a0 = f4add(a0, v0); a1 = f4add(a1, v1); a2 = f4add(a2, v2); a3 = f4add(a3, v3);
    }
    for (; j < jend; j++) {
        int s0 = d_csrc[j];
        a0 = f4add(a0, ((const float4*)(d_m + s0 * FEAT))[lane]);
    }
    a0 = f4add(f4add(a0, a1), f4add(a2, a3));
    ((float4*)(d_a + gw * FEAT))[lane] = a0;
}

// ---------------- fused: next-layer step 1 from factored linear ----------------
// m[n] = invdeg[n] * sum_{e: dst=n} relu( (g[src_e]+g[n])*0.5 + b )
__global__ void k_fused_agg(const float* __restrict__ b) {
    int gw = (blockIdx.x * blockDim.x + threadIdx.x) >> 5;
    if (gw >= N_NODES) return;
    int lane = threadIdx.x & 31;
    int j = d_rowptr[gw], jend = d_rowptr[gw + 1];
    float4 gn = ((const float4*)(d_g + gw * FEAT))[lane];
    float4 bv = __ldg(((const float4*)b) + lane);
    float4 a0 = {0, 0, 0, 0}, a1 = {0, 0, 0, 0};
    for (; j + 2 <= jend; j += 2) {
        int s0 = d_csrc[j], s1 = d_csrc[j + 1];
        float4 v0 = ((const float4*)(d_g + s0 * FEAT))[lane];
        float4 v1 = ((const float4*)(d_g + s1 * FEAT))[lane];
        a0.x += fmaxf((v0.x + gn.x) * 0.5f + bv.x, 0.f);
        a0.y += fmaxf((v0.y + gn.y) * 0.5f + bv.y, 0.f);
        a0.z += fmaxf((v0.z + gn.z) * 0.5f + bv.z, 0.f);
        a0.w += fmaxf((v0.w + gn.w) * 0.5f + bv.w, 0.f);
        a1.x += fmaxf((v1.x + gn.x) * 0.5f + bv.x, 0.f);
        a1.y += fmaxf((v1.y + gn.y) * 0.5f + bv.y, 0.f);
        a1.z += fmaxf((v1.z + gn.z) * 0.5f + bv.z, 0.f);
        a1.w += fmaxf((v1.w + gn.w) * 0.5f + bv.w, 0.f);
    }
    for (; j < jend; j++) {
        int s0 = d_csrc[j];
        float4 v0 = ((const float4*)(d_g + s0 * FEAT))[lane];
        a0.x += fmaxf((v0.x + gn.x) * 0.5f + bv.x, 0.f);
        a0.y += fmaxf((v0.y + gn.y) * 0.5f + bv.y, 0.f);
        a0.z += fmaxf((v0.z + gn.z) * 0.5f + bv.z, 0.f);
        a0.w += fmaxf((v0.w + gn.w) * 0.5f + bv.w, 0.f);
    }
    a0 = f4add(a0, a1);
    float id = d_invdeg[gw];
    float4 o = make_float4(a0.x * id, a0.y * id, a0.z * id, a0.w * id);
    ((float4*)(d_m + gw * FEAT))[lane] = o;
}

// ---------------- node-level GEMM: g = a @ W^T  (N x 128 @ 128 x OUT) ----------------
// 512 threads; each thread: 1 column, 8 rows. W transposed+padded in smem.
template <int OUT>
__global__ void k_node_gemm(const float* __restrict__ W) {
    constexpr int RG = 512 / OUT;
    constexpr int ROWS = RG * 8;
    extern __shared__ float smem[];
    float* sW = smem;                       // [128][OUT+1]
    float* sA = smem + 128 * (OUT + 1);     // [ROWS][128]
    int t = threadIdx.x;
    int col = t % OUT, rg = t / OUT;
    int row0 = blockIdx.x * ROWS;
    for (int i = t; i < OUT * 128; i += 512) {
        int c = i / 128, k = i % 128;
        sW[k * (OUT + 1) + c] = W[i];
    }
    for (int i = t; i < ROWS * 128; i += 512) {
        int r = i / 128, k = i % 128;
        int gr = row0 + r;
        sA[i] = (gr < N_NODES) ? d_a[gr * FEAT + k] : 0.f;
    }
    __syncthreads();
    float acc[8] = {0, 0, 0, 0, 0, 0, 0, 0};
    #pragma unroll 4
    for (int k = 0; k < 128; k++) {
        float wv = sW[k * (OUT + 1) + col];
        #pragma unroll
        for (int r = 0; r < 8; r++) acc[r] += sA[(rg * 8 + r) * 128 + k] * wv;
    }
    #pragma unroll
    for (int r = 0; r < 8; r++) {
        int gr = row0 + rg * 8 + r;
        if (gr < N_NODES) d_g[gr * OUT + col] = acc[r];
    }
}

// ---------------- final layer output: out[e] = (g5[src]+g5[dst])*0.5 + b5 ----------------
__global__ void k_final(const int* __restrict__ src, const int* __restrict__ dst,
                        const float* __restrict__ b, float* __restrict__ out) {
    int idx = blockIdx.x * blockDim.x + threadIdx.x;  // over E * 16 float4 chunks
    if (idx >= N_EDGES * (NCLS / 4)) return;
    int e = idx >> 4, c = idx & 15;
    int s = src[e], d = dst[e];
    float4 vs = ((const float4*)(d_g + s * NCLS))[c];
    float4 vd = ((const float4*)(d_g + d * NCLS))[c];
    float4 bv = __ldg(((const float4*)b) + c);
    float4 o = make_float4((vs.x + vd.x) * 0.5f + bv.x,
                           (vs.y + vd.y) * 0.5f + bv.y,
                           (vs.z + vd.z) * 0.5f + bv.z,
                           (vs.w + vd.w) * 0.5f + bv.w);
    ((float4*)out)[idx] = o;
}

// ---------------- launch ----------------
extern "C" void kernel_launch(void* const* d_in, const int* in_sizes, int n_in,
                              void* d_out, int out_size) {
    const float* edge_feats = (const float*)d_in[0];
    const int*   src        = (const int*)d_in[1];
    const int*   dst        = (const int*)d_in[2];
    const float* Ws[5] = {(const float*)d_in[3], (const float*)d_in[5],
                          (const float*)d_in[7], (const float*)d_in[9],
                          (const float*)d_in[11]};
    const float* bs[5] = {(const float*)d_in[4], (const float*)d_in[6],
                          (const float*)d_in[8], (const float*)d_in[10],
                          (const float*)d_in[12]};
    float* out = (float*)d_out;

    static bool attr_set = false;
    if (!attr_set) {
        cudaFuncSetAttribute(k_node_gemm<128>, cudaFuncAttributeMaxDynamicSharedMemorySize,
                             128 * 129 * 4 + 32 * 128 * 4);
        cudaFuncSetAttribute(k_node_gemm<64>, cudaFuncAttributeMaxDynamicSharedMemorySize,
                             128 * 65 * 4 + 64 * 128 * 4);
        attr_set = true;
    }

    // CSR build
    k_zero_deg<<<(N_NODES + 255) / 256, 256>>>();
    k_count<<<(N_EDGES + 255) / 256, 256>>>(dst);
    k_scan<<<1, 1024>>>();
    k_fill<<<(N_EDGES + 255) / 256, 256>>>(dst, src);

    const int GWBLK = 256;                       // 8 warps -> 8 nodes per block
    const int ngrid = (N_NODES * 32 + GWBLK - 1) / GWBLK;

    // layer 1 step 1 (edge_feats -> node mean)
    k_gather_mean_edges<<<ngrid, GWBLK>>>(edge_feats);

    const size_t smem128 = 128 * 129 * 4 + 32 * 128 * 4;
    const size_t smem64  = 128 * 65 * 4 + 64 * 128 * 4;
    const int g128 = (N_NODES + 31) / 32;   // 32 rows/block
    const int g64  = (N_NODES + 63) / 64;   // 64 rows/block

    for (int l = 0; l < 5; l++) {
        k_gather_sum_src<<<ngrid, GWBLK>>>();                 // step 2 -> d_a
        if (l < 4) {
            k_node_gemm<128><<<g128, 512, smem128>>>(Ws[l]);  // d_a @ W^T -> d_g
            k_fused_agg<<<ngrid, GWBLK>>>(bs[l]);             // relu edge + next mean -> d_m
        } else {
            k_node_gemm<64><<<g64, 512, smem64>>>(Ws[l]);
        }
    }
    k_final<<<(N_EDGES * (NCLS / 4) + 255) / 256, 256>>>(src, dst, bs[4], out);
}

// round 2
// speedup vs baseline: 1.0259x; 1.0259x over previous
#include <cuda_runtime.h>
#include <cuda_fp16.h>
#include <cstdint>

#define N_NODES 10000
#define N_EDGES 320000
#define FEAT 128
#define NCLS 64

// ---------------- scratch (no allocations allowed) ----------------
__device__ int    d_deg[N_NODES];
__device__ int    d_rowptr[N_NODES + 1];
__device__ int    d_cursor[N_NODES];
__device__ int    d_eidx[N_EDGES];   // edge ids sorted by dst (CSR)
__device__ int    d_csrc[N_EDGES];   // src[eidx[j]] pre-gathered
__device__ float  d_invdeg[N_NODES];
__device__ __half d_mh[N_NODES * FEAT];  // node mean buffer (fp16)
__device__ float  d_a [N_NODES * FEAT];  // node sum buffer (GEMM input, fp32)
__device__ __half d_gh[N_NODES * FEAT];  // node GEMM output (fp16)

__device__ __forceinline__ float4 f4add(float4 a, float4 b) {
    return make_float4(a.x + b.x, a.y + b.y, a.z + b.z, a.w + b.w);
}

// load 4 halves (uint2) -> float4
__device__ __forceinline__ float4 ld_h4(const uint2* p) {
    uint2 u = *p;
    __half2 h0 = *reinterpret_cast<__half2*>(&u.x);
    __half2 h1 = *reinterpret_cast<__half2*>(&u.y);
    float2 f0 = __half22float2(h0), f1 = __half22float2(h1);
    return make_float4(f0.x, f0.y, f1.x, f1.y);
}
// store float4 -> 4 halves (uint2)
__device__ __forceinline__ void st_h4(uint2* p, float4 v) {
    __half2 h0 = __floats2half2_rn(v.x, v.y);
    __half2 h1 = __floats2half2_rn(v.z, v.w);
    uint2 u;
    u.x = *reinterpret_cast<unsigned int*>(&h0);
    u.y = *reinterpret_cast<unsigned int*>(&h1);
    *p = u;
}

// ---------------- CSR construction ----------------
__global__ void k_zero_deg() {
    int i = blockIdx.x * blockDim.x + threadIdx.x;
    if (i < N_NODES) d_deg[i] = 0;
}

__global__ void k_count(const int* __restrict__ dst) {
    int e = blockIdx.x * blockDim.x + threadIdx.x;
    if (e < N_EDGES) atomicAdd(&d_deg[dst[e]], 1);
}

// single-block scan (1024 threads x 10 items)
__global__ void k_scan() {
    __shared__ int tsum[1024];
    const int IPT = 10;
    int t = threadIdx.x;
    int base = t * IPT;
    int local[IPT];
    int s = 0;
    #pragma unroll
    for (int i = 0; i < IPT; i++) {
        int idx = base + i;
        int v = (idx < N_NODES) ? d_deg[idx] : 0;
        local[i] = s;
        s += v;
    }
    tsum[t] = s;
    __syncthreads();
    for (int d = 1; d < 1024; d <<= 1) {
        int v = (t >= d) ? tsum[t - d] : 0;
        __syncthreads();
        tsum[t] += v;
        __syncthreads();
    }
    int offset = tsum[t] - s;  // exclusive
    #pragma unroll
    for (int i = 0; i < IPT; i++) {
        int idx = base + i;
        if (idx < N_NODES) {
            int rp = offset + local[i];
            d_rowptr[idx] = rp;
            d_cursor[idx] = rp;
            d_invdeg[idx] = 1.0f / (float)d_deg[idx];
        }
    }
    if (t == 1023) d_rowptr[N_NODES] = tsum[1023];
}

__global__ void k_fill(const int* __restrict__ dst, const int* __restrict__ src) {
    int e = blockIdx.x * blockDim.x + threadIdx.x;
    if (e < N_EDGES) {
        int pos = atomicAdd(&d_cursor[dst[e]], 1);
        d_eidx[pos] = e;
        d_csrc[pos] = src[e];
    }
}

// ---------------- layer-1 step 1: m[n] = mean over in-edges of edge_feats ----------------
// warp per node, float4 per lane (fp32 input from HBM), fp16 output
__global__ void k_gather_mean_edges(const float* __restrict__ ef) {
    int gw = (blockIdx.x * blockDim.x + threadIdx.x) >> 5;
    if (gw >= N_NODES) return;
    int lane = threadIdx.x & 31;
    int j = d_rowptr[gw], jend = d_rowptr[gw + 1];
    float4 a0 = {0, 0, 0, 0}, a1 = {0, 0, 0, 0}, a2 = {0, 0, 0, 0}, a3 = {0, 0, 0, 0};
    for (; j + 4 <= jend; j += 4) {
        int e0 = d_eidx[j], e1 = d_eidx[j + 1], e2 = d_eidx[j + 2], e3 = d_eidx[j + 3];
        float4 v0 = __ldg(((const float4*)(ef + (size_t)e0 * FEAT)) + lane);
        float4 v1 = __ldg(((const float4*)(ef + (size_t)e1 * FEAT)) + lane);
        float4 v2 = __ldg(((const float4*)(ef + (size_t)e2 * FEAT)) + lane);
        float4 v3 = __ldg(((const float4*)(ef + (size_t)e3 * FEAT)) + lane);
        a0 = f4add(a0, v0); a1 = f4add(a1, v1); a2 = f4add(a2, v2); a3 = f4add(a3, v3);
    }
    for (; j < jend; j++) {
        int e0 = d_eidx[j];
        a0 = f4add(a0, __ldg(((const float4*)(ef + (size_t)e0 * FEAT)) + lane));
    }
    a0 = f4add(f4add(a0, a1), f4add(a2, a3));
    float id = d_invdeg[gw];
    float4 o = make_float4(a0.x * id, a0.y * id, a0.z * id, a0.w * id);
    st_h4(((uint2*)(d_mh + gw * FEAT)) + lane, o);
}

// ---------------- step 2: a[n] = sum over in-edges of m[src_e]  (fp16 gather, fp32 acc) ----
__global__ void k_gather_sum_src() {
    int gw = (blockIdx.x * blockDim.x + threadIdx.x) >> 5;
    if (gw >= N_NODES) return;
    int lane = threadIdx.x & 31;
    int j = d_rowptr[gw], jend = d_rowptr[gw + 1];
    float4 a0 = {0, 0, 0, 0}, a1 = {0, 0, 0, 0}, a2 = {0, 0, 0, 0}, a3 = {0, 0, 0, 0};
    for (; j + 4 <= jend; j += 4) {
        int s0 = d_csrc[j], s1 = d_csrc[j + 1], s2 = d_csrc[j + 2], s3 = d_csrc[j + 3];
        float4 v0 = ld_h4(((const uint2*)(d_mh + s0 * FEAT)) + lane);
        float4 v1 = ld_h4(((const uint2*)(d_mh + s1 * FEAT)) + lane);
        float4 v2 = ld_h4(((const uint2*)(d_mh + s2 * FEAT)) + lane);
        float4 v3 = ld_h4(((const uint2*)(d_mh + s3 * FEAT)) + lane);
        a0 = f4add(a0, v0); a1 = f4add(a1, v1); a2 = f4add(a2, v2); a3 = f4add(a3, v3);
    }
    for (; j < jend; j++) {
        int s0 = d_csrc[j];
        a0 = f4add(a0, ld_h4(((const uint2*)(d_mh + s0 * FEAT)) + lane));
    }
    a0 = f4add(f4add(a0, a1), f4add(a2, a3));
    ((float4*)(d_a + gw * FEAT))[lane] = a0;
}

// ---------------- fused: next-layer step 1 from factored linear ----------------
// m[n] = invdeg[n] * sum_{e: dst=n} relu( (g[src_e]+g[n])*0.5 + b )
__global__ void k_fused_agg(const float* __restrict__ b) {
    int gw = (blockIdx.x * blockDim.x + threadIdx.x) >> 5;
    if (gw >= N_NODES) return;
    int lane = threadIdx.x & 31;
    int j = d_rowptr[gw], jend = d_rowptr[gw + 1];
    float4 gn = ld_h4(((const uint2*)(d_gh + gw * FEAT)) + lane);
    float4 bv = __ldg(((const float4*)b) + lane);
    // fold: relu((gs+gn)*0.5+b) = relu(0.5*gs + c) with c = 0.5*gn + b
    float4 c = make_float4(gn.x * 0.5f + bv.x, gn.y * 0.5f + bv.y,
                           gn.z * 0.5f + bv.z, gn.w * 0.5f + bv.w);
    float4 a0 = {0, 0, 0, 0}, a1 = {0, 0, 0, 0};
    for (; j + 4 <= jend; j += 4) {
        int s0 = d_csrc[j], s1 = d_csrc[j + 1], s2 = d_csrc[j + 2], s3 = d_csrc[j + 3];
        float4 v0 = ld_h4(((const uint2*)(d_gh + s0 * FEAT)) + lane);
        float4 v1 = ld_h4(((const uint2*)(d_gh + s1 * FEAT)) + lane);
        float4 v2 = ld_h4(((const uint2*)(d_gh + s2 * FEAT)) + lane);
        float4 v3 = ld_h4(((const uint2*)(d_gh + s3 * FEAT)) + lane);
        a0.x += fmaxf(fmaf(v0.x, 0.5f, c.x), 0.f) + fmaxf(fmaf(v2.x, 0.5f, c.x), 0.f);
        a0.y += fmaxf(fmaf(v0.y, 0.5f, c.y), 0.f) + fmaxf(fmaf(v2.y, 0.5f, c.y), 0.f);
        a0.z += fmaxf(fmaf(v0.z, 0.5f, c.z), 0.f) + fmaxf(fmaf(v2.z, 0.5f, c.z), 0.f);
        a0.w += fmaxf(fmaf(v0.w, 0.5f, c.w), 0.f) + fmaxf(fmaf(v2.w, 0.5f, c.w), 0.f);
        a1.x += fmaxf(fmaf(v1.x, 0.5f, c.x), 0.f) + fmaxf(fmaf(v3.x, 0.5f, c.x), 0.f);
        a1.y += fmaxf(fmaf(v1.y, 0.5f, c.y), 0.f) + fmaxf(fmaf(v3.y, 0.5f, c.y), 0.f);
        a1.z += fmaxf(fmaf(v1.z, 0.5f, c.z), 0.f) + fmaxf(fmaf(v3.z, 0.5f, c.z), 0.f);
        a1.w += fmaxf(fmaf(v1.w, 0.5f, c.w), 0.f) + fmaxf(fmaf(v3.w, 0.5f, c.w), 0.f);
    }
    for (; j < jend; j++) {
        int s0 = d_csrc[j];
        float4 v0 = ld_h4(((const uint2*)(d_gh + s0 * FEAT)) + lane);
        a0.x += fmaxf(fmaf(v0.x, 0.5f, c.x), 0.f);
        a0.y += fmaxf(fmaf(v0.y, 0.5f, c.y), 0.f);
        a0.z += fmaxf(fmaf(v0.z, 0.5f, c.z), 0.f);
        a0.w += fmaxf(fmaf(v0.w, 0.5f, c.w), 0.f);
    }
    a0 = f4add(a0, a1);
    float id = d_invdeg[gw];
    float4 o = make_float4(a0.x * id, a0.y * id, a0.z * id, a0.w * id);
    st_h4(((uint2*)(d_mh + gw * FEAT)) + lane, o);
}

// ---------------- node-level GEMM: g = a @ W^T  (N x 128 @ 128 x OUT), fp16 out ----------
template <int OUT>
__global__ void k_node_gemm(const float* __restrict__ W) {
    constexpr int RG = 512 / OUT;
    constexpr int ROWS = RG * 8;
    extern __shared__ float smem[];
    float* sW = smem;                       // [128][OUT+1]
    float* sA = smem + 128 * (OUT + 1);     // [ROWS][128]
    int t = threadIdx.x;
    int col = t % OUT, rg = t / OUT;
    int row0 = blockIdx.x * ROWS;
    for (int i = t; i < OUT * 128; i += 512) {
        int c = i / 128, k = i % 128;
        sW[k * (OUT + 1) + c] = W[i];
    }
    for (int i = t; i < ROWS * 128; i += 512) {
        int r = i / 128, k = i % 128;
        int gr = row0 + r;
        sA[i] = (gr < N_NODES) ? d_a[gr * FEAT + k] : 0.f;
    }
    __syncthreads();
    float acc[8] = {0, 0, 0, 0, 0, 0, 0, 0};
    #pragma unroll 4
    for (int k = 0; k < 128; k++) {
        float wv = sW[k * (OUT + 1) + col];
        #pragma unroll
        for (int r = 0; r < 8; r++) acc[r] += sA[(rg * 8 + r) * 128 + k] * wv;
    }
    #pragma unroll
    for (int r = 0; r < 8; r++) {
        int gr = row0 + rg * 8 + r;
        if (gr < N_NODES) d_gh[gr * OUT + col] = __float2half_rn(acc[r]);
    }
}

// ---------------- final layer output: out[e] = (g5[src]+g5[dst])*0.5 + b5 ----------------
__global__ void k_final(const int* __restrict__ src, const int* __restrict__ dst,
                        const float* __restrict__ b, float* __restrict__ out) {
    int idx = blockIdx.x * blockDim.x + threadIdx.x;  // over E * 16 chunks of 4 cols
    if (idx >= N_EDGES * (NCLS / 4)) return;
    int e = idx >> 4, c = idx & 15;
    int s = src[e], d = dst[e];
    float4 vs = ld_h4(((const uint2*)(d_gh + s * NCLS)) + c);
    float4 vd = ld_h4(((const uint2*)(d_gh + d * NCLS)) + c);
    float4 bv = __ldg(((const float4*)b) + c);
    float4 o = make_float4((vs.x + vd.x) * 0.5f + bv.x,
                           (vs.y + vd.y) * 0.5f + bv.y,
                           (vs.z + vd.z) * 0.5f + bv.z,
                           (vs.w + vd.w) * 0.5f + bv.w);
    ((float4*)out)[idx] = o;
}

// ---------------- launch ----------------
extern "C" void kernel_launch(void* const* d_in, const int* in_sizes, int n_in,
                              void* d_out, int out_size) {
    const float* edge_feats = (const float*)d_in[0];
    const int*   src        = (const int*)d_in[1];
    const int*   dst        = (const int*)d_in[2];
    const float* Ws[5] = {(const float*)d_in[3], (const float*)d_in[5],
                          (const float*)d_in[7], (const float*)d_in[9],
                          (const float*)d_in[11]};
    const float* bs[5] = {(const float*)d_in[4], (const float*)d_in[6],
                          (const float*)d_in[8], (const float*)d_in[10],
                          (const float*)d_in[12]};
    float* out = (float*)d_out;

    cudaFuncSetAttribute(k_node_gemm<128>, cudaFuncAttributeMaxDynamicSharedMemorySize,
                         128 * 129 * 4 + 32 * 128 * 4);
    cudaFuncSetAttribute(k_node_gemm<64>, cudaFuncAttributeMaxDynamicSharedMemorySize,
                         128 * 65 * 4 + 64 * 128 * 4);

    // CSR build
    k_zero_deg<<<(N_NODES + 255) / 256, 256>>>();
    k_count<<<(N_EDGES + 255) / 256, 256>>>(dst);
    k_scan<<<1, 1024>>>();
    k_fill<<<(N_EDGES + 255) / 256, 256>>>(dst, src);

    const int GWBLK = 256;                       // 8 warps -> 8 nodes per block
    const int ngrid = (N_NODES * 32 + GWBLK - 1) / GWBLK;

    // layer 1 step 1 (edge_feats -> node mean)
    k_gather_mean_edges<<<ngrid, GWBLK>>>(edge_feats);

    const size_t smem128 = 128 * 129 * 4 + 32 * 128 * 4;
    const size_t smem64  = 128 * 65 * 4 + 64 * 128 * 4;
    const int g128 = (N_NODES + 31) / 32;   // 32 rows/block
    const int g64  = (N_NODES + 63) / 64;   // 64 rows/block

    for (int l = 0; l < 5; l++) {
        k_gather_sum_src<<<ngrid, GWBLK>>>();                 // step 2 -> d_a
        if (l < 4) {
            k_node_gemm<128><<<g128, 512, smem128>>>(Ws[l]);  // d_a @ W^T -> d_gh
            k_fused_agg<<<ngrid, GWBLK>>>(bs[l]);             // relu edge + next mean -> d_mh
        } else {
            k_node_gemm<64><<<g64, 512, smem64>>>(Ws[l]);
        }
    }
    k_final<<<(N_EDGES * (NCLS / 4) + 255) / 256, 256>>>(src, dst, bs[4], out);
}